// round 12
// baseline (speedup 1.0000x reference)
#include <cuda_runtime.h>
#include <math.h>

#define B_   1024
#define D_   768
#define E_   1536
#define C_   150
#define P_   64
#define CPAD 160
#define NC_  151
#define UZ   16          // split-K slices for u
#define SZ   16          // e-splits for seen

typedef unsigned long long ull;

// ------------------------- f32x2 packed-math helpers -------------------------
__device__ __forceinline__ ull pack2(float x, float y) {
    ull r; asm("mov.b64 %0, {%1,%2};" : "=l"(r) : "f"(x), "f"(y)); return r;
}
__device__ __forceinline__ void unpack2(ull v, float& x, float& y) {
    asm("mov.b64 {%0,%1}, %2;" : "=f"(x), "=f"(y) : "l"(v));
}
__device__ __forceinline__ ull ffma2(ull a, ull b, ull c) {
    ull d; asm("fma.rn.f32x2 %0, %1, %2, %3;" : "=l"(d) : "l"(a), "l"(b), "l"(c)); return d;
}
// relu(a + m) on both packed halves
__device__ __forceinline__ ull addrelu2(ull a, ull m) {
    ull r;
    asm("{\n\t"
        ".reg .b64 s;\n\t"
        ".reg .f32 lo, hi;\n\t"
        "add.rn.f32x2 s, %1, %2;\n\t"
        "mov.b64 {lo, hi}, s;\n\t"
        "max.f32 lo, lo, 0f00000000;\n\t"
        "max.f32 hi, hi, 0f00000000;\n\t"
        "mov.b64 %0, {lo, hi};\n\t"
        "}" : "=l"(r) : "l"(a), "l"(m));
    return r;
}

// ------------------------- static device scratch -------------------------
__device__ float g_xh[B_ * E_];                 // x @ Wx^T + fc_b
__device__ float g_mh[C_ * E_];                 // mem @ Wm^T
__device__ float g_seen_part[SZ * B_ * CPAD];   // e-split partials of logits
__device__ float g_u_part[UZ * B_ * P_];        // split-K partials of u
__device__ float g_un[B_ * P_];                 // normalized u
__device__ float g_sqn[B_];                     // ||un||^2 (post-normalize)
__device__ float g_lossrow[B_];
__device__ float g_pp[256 * 4];                 // per-block pair partials

// ------------------------- BM=64 f32x2 GEMM core (256 threads) -------------------------
// C[m0+i, n0+j] = sum_k A[m0+i, kbase+k] * W[n0+j, koff+kbase+k]  (+bias)
// BM=64, BN in {128,64}; micro-tile 4 x (BN/16). A duplicated in smem
// (LDS.64 -> (a,a) operand); W pairs read as ulonglong2.
template <int BN, bool RELU_A>
__device__ __forceinline__ void gemm64(
    const float* __restrict__ A, int M, int m0, int lda,
    const float* __restrict__ W, int n0, int ldw, int koff,
    int kbase, int klen, const float* __restrict__ bias,
    float* __restrict__ out, int ldc)
{
    constexpr int MJ = BN / 16;          // cols per thread (8 or 4)
    constexpr int WL = BN / 128;         // extra W float4 loads (1 or 0)
    __shared__ float As2[16][132];       // duplicated A pairs [k][2*row]
    __shared__ float Ws[16][BN + 4];

    const int t  = threadIdx.x;
    const int tx = t & 15;               // col group
    const int ty = t >> 4;               // row group (16 x 4 rows)
    const int arow = t >> 2, aq = t & 3; // A/W tile loader coords

    ull acc[4][MJ / 2];
#pragma unroll
    for (int i = 0; i < 4; i++)
#pragma unroll
        for (int j = 0; j < MJ / 2; j++) acc[i][j] = 0ull;

    float4 pa, pw[1 + WL];

    // prefetch first k-tile
    {
        float4 v = make_float4(0.f, 0.f, 0.f, 0.f);
        const int am = m0 + arow;
        if (am < M) v = *(const float4*)(A + (long long)am * lda + kbase + aq * 4);
        if (RELU_A) {
            v.x = fmaxf(v.x, 0.f); v.y = fmaxf(v.y, 0.f);
            v.z = fmaxf(v.z, 0.f); v.w = fmaxf(v.w, 0.f);
        }
        pa = v;
#pragma unroll
        for (int l = 0; l < 1 + WL; l++) {
            const int idx = t + 256 * l;
            const int row = idx >> 2, q = idx & 3;
            pw[l] = *(const float4*)(W + (long long)(n0 + row) * ldw + koff + kbase + q * 4);
        }
    }

    const int nktiles = klen / 16;
    for (int kt = 0; kt < nktiles; kt++) {
        __syncthreads();
        {
            const float4 v = pa;
            *(ull*)&As2[aq * 4 + 0][2 * arow] = pack2(v.x, v.x);
            *(ull*)&As2[aq * 4 + 1][2 * arow] = pack2(v.y, v.y);
            *(ull*)&As2[aq * 4 + 2][2 * arow] = pack2(v.z, v.z);
            *(ull*)&As2[aq * 4 + 3][2 * arow] = pack2(v.w, v.w);
        }
#pragma unroll
        for (int l = 0; l < 1 + WL; l++) {
            const int idx = t + 256 * l;
            const int row = idx >> 2, q = idx & 3;
            const float4 v = pw[l];
            Ws[q * 4 + 0][row] = v.x; Ws[q * 4 + 1][row] = v.y;
            Ws[q * 4 + 2][row] = v.z; Ws[q * 4 + 3][row] = v.w;
        }
        __syncthreads();

        // prefetch next tile
        if (kt + 1 < nktiles) {
            const int kn = kbase + (kt + 1) * 16;
            float4 v = make_float4(0.f, 0.f, 0.f, 0.f);
            const int am = m0 + arow;
            if (am < M) v = *(const float4*)(A + (long long)am * lda + kn + aq * 4);
            if (RELU_A) {
                v.x = fmaxf(v.x, 0.f); v.y = fmaxf(v.y, 0.f);
                v.z = fmaxf(v.z, 0.f); v.w = fmaxf(v.w, 0.f);
            }
            pa = v;
#pragma unroll
            for (int l = 0; l < 1 + WL; l++) {
                const int idx = t + 256 * l;
                const int row = idx >> 2, q = idx & 3;
                pw[l] = *(const float4*)(W + (long long)(n0 + row) * ldw + koff + kn + q * 4);
            }
        }

        // compute
#pragma unroll
        for (int kk = 0; kk < 16; kk++) {
            ull av[4];
#pragma unroll
            for (int i = 0; i < 4; i++)
                av[i] = *(const ull*)&As2[kk][2 * (ty * 4 + i)];
            ull bv[MJ / 2];
            if constexpr (MJ == 8) {
                const ulonglong2 w0 = *(const ulonglong2*)&Ws[kk][tx * 8];
                const ulonglong2 w1 = *(const ulonglong2*)&Ws[kk][tx * 8 + 4];
                bv[0] = w0.x; bv[1] = w0.y; bv[2] = w1.x; bv[3] = w1.y;
            } else {
                const ulonglong2 w0 = *(const ulonglong2*)&Ws[kk][tx * 4];
                bv[0] = w0.x; bv[1] = w0.y;
            }
#pragma unroll
            for (int i = 0; i < 4; i++)
#pragma unroll
                for (int j = 0; j < MJ / 2; j++)
                    acc[i][j] = ffma2(av[i], bv[j], acc[i][j]);
        }
    }

    const int nb = n0 + tx * MJ;
    float bvv[MJ];
#pragma unroll
    for (int q = 0; q < MJ; q++) bvv[q] = (bias != nullptr) ? bias[nb + q] : 0.f;
#pragma unroll
    for (int i = 0; i < 4; i++) {
        const int m = m0 + ty * 4 + i;
        if (m >= M) continue;
        float o[MJ];
#pragma unroll
        for (int jp = 0; jp < MJ / 2; jp++) unpack2(acc[i][jp], o[2 * jp], o[2 * jp + 1]);
#pragma unroll
        for (int q = 0; q < MJ; q++) o[q] += bvv[q];
#pragma unroll
        for (int q = 0; q < MJ / 4; q++)
            *(float4*)(out + (long long)m * ldc + nb + 4 * q) =
                make_float4(o[4 * q], o[4 * q + 1], o[4 * q + 2], o[4 * q + 3]);
    }
}

// combined xh (bx<16) and mh (bx>=16); grid (19, 12) = 228 blocks
__global__ __launch_bounds__(256) void gemm_xhmh(
    const float* __restrict__ x, const float* __restrict__ mem,
    const float* __restrict__ fc_w, const float* __restrict__ fc_b,
    float* __restrict__ xh, float* __restrict__ mh)
{
    const int bx = blockIdx.x;
    const int n0 = blockIdx.y * 128;
    const float* A; int M, m0, koff; const float* bias; float* out;
    if (bx < 16) { A = x;   M = B_; m0 = bx * 64;        koff = 0;  bias = fc_b;   out = xh; }
    else         { A = mem; M = C_; m0 = (bx - 16) * 64; koff = D_; bias = nullptr; out = mh; }
    gemm64<128, false>(A, M, m0, D_, fc_w, n0, E_, koff, 0, D_, bias, out, E_);
}

// u partials: relu(xh) @ p2_w^T, split-K = UZ chunks of 96; grid (16,1,16)=256
__global__ __launch_bounds__(256) void gemm_u(
    const float* __restrict__ xh, const float* __restrict__ p2w,
    float* __restrict__ outbase)
{
    const int z = blockIdx.z;
    constexpr int CHUNK = E_ / UZ;   // 96
    gemm64<64, true>(xh, B_, blockIdx.x * 64, E_, p2w, 0, E_, 0,
                     z * CHUNK, CHUNK, nullptr,
                     outbase + (long long)z * (B_ * P_), P_);
}

// ------------------------- seen/unseen fused -------------------------
// part[z][b][c] = sum_{e in z-chunk(96)} relu(xh[b,e] + mh_ext[c,e]) * p1w[e]
// class 150 == "unseen" (mh row = 0). Block: 64 b x 160 c; grid (16, SZ) = 256.
// Ms stored duplicated -> (m,m) packed operand in one LDS.64; b-pairs natural.
__global__ __launch_bounds__(256) void seen_kernel(const float* __restrict__ p1w)
{
    __shared__ float As[16][68];     // [e][b]
    __shared__ float Ms2[16][324];   // [e][2c / 2c+1] duplicated
    __shared__ float Wsh[16];

    const int t  = threadIdx.x;
    const int tx = t & 31;           // c lane
    const int ty = t >> 5;           // b group (0..7)
    const int b0 = blockIdx.x * 64;
    const int e0 = blockIdx.y * 96;  // SZ splits of 96

    ull acc[4][5];
#pragma unroll
    for (int p = 0; p < 4; p++)
#pragma unroll
        for (int j = 0; j < 5; j++) acc[p][j] = 0ull;

    for (int ch = 0; ch < 6; ch++) {
        const int ec = e0 + ch * 16;
        __syncthreads();
        // xh tile 64 x 16 : 256 float4, 1/thread
        {
            const int row = t >> 2, c4 = t & 3;
            const float4 v = *(const float4*)(g_xh + (long long)(b0 + row) * E_ + ec + c4 * 4);
            As[c4 * 4 + 0][row] = v.x; As[c4 * 4 + 1][row] = v.y;
            As[c4 * 4 + 2][row] = v.z; As[c4 * 4 + 3][row] = v.w;
        }
        // mh tile 160 x 16 duplicated : 640 float4
        for (int idx = t; idx < 640; idx += 256) {
            const int c = idx >> 2, c4 = idx & 3;
            float4 v = make_float4(0.f, 0.f, 0.f, 0.f);
            if (c < C_) v = *(const float4*)(g_mh + (long long)c * E_ + ec + c4 * 4);
            *(ull*)&Ms2[c4 * 4 + 0][2 * c] = pack2(v.x, v.x);
            *(ull*)&Ms2[c4 * 4 + 1][2 * c] = pack2(v.y, v.y);
            *(ull*)&Ms2[c4 * 4 + 2][2 * c] = pack2(v.z, v.z);
            *(ull*)&Ms2[c4 * 4 + 3][2 * c] = pack2(v.w, v.w);
        }
        if (t < 16) Wsh[t] = p1w[ec + t];
        __syncthreads();

#pragma unroll 4
        for (int e = 0; e < 16; e++) {
            const float w = Wsh[e];
            const ull w2 = pack2(w, w);
            ull av[4];
#pragma unroll
            for (int p = 0; p < 4; p++)
                av[p] = *(const ull*)&As[e][ty * 8 + 2 * p];
            ull m2[5];
#pragma unroll
            for (int j = 0; j < 5; j++)
                m2[j] = *(const ull*)&Ms2[e][2 * (tx + 32 * j)];
#pragma unroll
            for (int j = 0; j < 5; j++)
#pragma unroll
                for (int p = 0; p < 4; p++)
                    acc[p][j] = ffma2(addrelu2(av[p], m2[j]), w2, acc[p][j]);
        }
    }

    float* outp = g_seen_part + (long long)blockIdx.y * (B_ * CPAD);
#pragma unroll
    for (int p = 0; p < 4; p++) {
        float f0, f1;
#pragma unroll
        for (int j = 0; j < 5; j++) {
            unpack2(acc[p][j], f0, f1);
            const int c = tx + 32 * j;
            outp[(long long)(b0 + ty * 8 + 2 * p)     * CPAD + c] = f0;
            outp[(long long)(b0 + ty * 8 + 2 * p + 1) * CPAD + c] = f1;
        }
    }
}

// ------------------------- warp reduce helpers -------------------------
__device__ __forceinline__ float warp_max(float v) {
#pragma unroll
    for (int o = 16; o > 0; o >>= 1) v = fmaxf(v, __shfl_xor_sync(0xffffffffu, v, o));
    return v;
}
__device__ __forceinline__ float warp_sum(float v) {
#pragma unroll
    for (int o = 16; o > 0; o >>= 1) v += __shfl_xor_sync(0xffffffffu, v, o);
    return v;
}

// per-row: sum e-split partials -> logits, then masked-softmax losses
__global__ __launch_bounds__(256) void rowloss_kernel(const int* __restrict__ lb,
                                                      const float* __restrict__ p1b)
{
    const int warp = threadIdx.x >> 5;
    const int lane = threadIdx.x & 31;
    const int b = blockIdx.x * 8 + warp;
    if (b >= B_) return;
    const int label = lb[b];
    const float bias0 = p1b[0];

    float raw[5];
#pragma unroll
    for (int it = 0; it < 5; it++) {
        const int c = lane + 32 * it;
        float s = bias0;
        if (c < NC_) {
#pragma unroll
            for (int zz = 0; zz < SZ; zz++)
                s += g_seen_part[(long long)zz * (B_ * CPAD) + (long long)b * CPAD + c];
            raw[it] = s;
        } else raw[it] = -3.0e38f;
    }

    const float l150 = __shfl_sync(0xffffffffu, raw[4], NC_ - 1 - 128);
    float lv = -3.0e38f;
#pragma unroll
    for (int it = 0; it < 5; it++)
        if (lane + 32 * it == label) lv = raw[it];
    lv = warp_max(lv);

    float vmax = -3.0e38f;
    float ex[5];
#pragma unroll
    for (int it = 0; it < 5; it++) {
        float v = raw[it];
        if (label < C_ && (lane + 32 * it) == label) v = -3.0e38f;
        ex[it] = v;
        vmax = fmaxf(vmax, v);
    }
    const float m2 = warp_max(vmax);
    float s = 0.f;
#pragma unroll
    for (int it = 0; it < 5; it++)
        if (ex[it] > -1.0e38f) s += expf(ex[it] - m2);
    const float s2 = warp_sum(s);

    if (lane == 0) {
        const float loss2 = -(l150 - (m2 + logf(s2)));
        float loss1 = 0.f;
        if (label < C_) {
            const float mm = fmaxf(lv, l150);
            const float ss = expf(lv - mm) + expf(l150 - mm);
            loss1 = -(lv - (mm + logf(ss)));
        }
        g_lossrow[b] = loss1 + loss2;
    }
}

// finalize u: sum split-K partials + bias, L2-normalize, store ||un||^2
__global__ __launch_bounds__(256) void u_final_kernel(const float* __restrict__ p2b)
{
    const int warp = threadIdx.x >> 5;
    const int lane = threadIdx.x & 31;
    const int b = blockIdx.x * 8 + warp;
    if (b >= B_) return;

    float v0 = p2b[lane], v1 = p2b[lane + 32];
#pragma unroll
    for (int z = 0; z < UZ; z++) {
        const float* p = g_u_part + (long long)z * (B_ * P_) + (long long)b * P_;
        v0 += p[lane];
        v1 += p[lane + 32];
    }
    const float n2 = warp_sum(v0 * v0 + v1 * v1);
    const float n = fmaxf(sqrtf(n2), 1e-12f);
    const float u0 = v0 / n, u1 = v1 / n;
    g_un[(long long)b * P_ + lane]      = u0;
    g_un[(long long)b * P_ + lane + 32] = u1;
    const float sq = warp_sum(u0 * u0 + u1 * u1);
    if (lane == 0) g_sqn[b] = sq;
}

// pairwise contrastive terms: 64x64 pair tile / block, K=64 dots via FFMA2
__global__ __launch_bounds__(256) void pairs_kernel(const int* __restrict__ lb)
{
    __shared__ float Ui[64][68];
    __shared__ float Uj[64][68];
    __shared__ int   lbi[64], lbj[64];
    __shared__ float sqi[64], sqj[64];
    __shared__ float red[8][4];

    const int t  = threadIdx.x;
    const int tx = t & 15, ty = t >> 4;
    const int i0 = blockIdx.x * 64, j0 = blockIdx.y * 64;

    for (int idx = t; idx < 1024; idx += 256) {
        const int row = idx >> 4, c4 = idx & 15;
        float4 v = *(const float4*)(g_un + (long long)(i0 + row) * P_ + c4 * 4);
        Ui[c4 * 4 + 0][row] = v.x; Ui[c4 * 4 + 1][row] = v.y;
        Ui[c4 * 4 + 2][row] = v.z; Ui[c4 * 4 + 3][row] = v.w;
        v = *(const float4*)(g_un + (long long)(j0 + row) * P_ + c4 * 4);
        Uj[c4 * 4 + 0][row] = v.x; Uj[c4 * 4 + 1][row] = v.y;
        Uj[c4 * 4 + 2][row] = v.z; Uj[c4 * 4 + 3][row] = v.w;
    }
    if (t < 64)       { lbi[t] = lb[i0 + t];           sqi[t] = g_sqn[i0 + t]; }
    else if (t < 128) { lbj[t - 64] = lb[j0 + t - 64]; sqj[t - 64] = g_sqn[j0 + t - 64]; }
    __syncthreads();

    ull dot2[4][2];
#pragma unroll
    for (int i = 0; i < 4; i++) { dot2[i][0] = 0ull; dot2[i][1] = 0ull; }

#pragma unroll 8
    for (int kk = 0; kk < 64; kk++) {
        const float4 a = *(const float4*)&Ui[kk][ty * 4];
        const float4 b = *(const float4*)&Uj[kk][tx * 4];
        const ull b01 = pack2(b.x, b.y);
        const ull b23 = pack2(b.z, b.w);
        const float aa[4] = {a.x, a.y, a.z, a.w};
#pragma unroll
        for (int i = 0; i < 4; i++) {
            const ull ai = pack2(aa[i], aa[i]);
            dot2[i][0] = ffma2(ai, b01, dot2[i][0]);
            dot2[i][1] = ffma2(ai, b23, dot2[i][1]);
        }
    }

    float ps = 0.f, pc = 0.f, ns = 0.f, nc = 0.f;
#pragma unroll
    for (int i = 0; i < 4; i++) {
        const int li = ty * 4 + i;
        float dd[4];
        unpack2(dot2[i][0], dd[0], dd[1]);
        unpack2(dot2[i][1], dd[2], dd[3]);
#pragma unroll
        for (int j = 0; j < 4; j++) {
            const int ljj = tx * 4 + j;
            const float sq = sqi[li] + sqj[ljj] - 2.f * dd[j];
            const float d = (sq > 0.f) ? sqrtf(fmaxf(sq, 1e-16f)) : 0.f;
            if (lbi[li] == lbj[ljj]) {
                if ((i0 + li) != (j0 + ljj)) { ps += fmaxf(d - 0.7f, 0.f); pc += 1.f; }
            } else {
                ns += fmaxf(1.4f - d, 0.f); nc += 1.f;
            }
        }
    }
    ps = warp_sum(ps); pc = warp_sum(pc); ns = warp_sum(ns); nc = warp_sum(nc);
    const int warp = t >> 5, lane = t & 31;
    if (lane == 0) { red[warp][0] = ps; red[warp][1] = pc; red[warp][2] = ns; red[warp][3] = nc; }
    __syncthreads();
    if (t == 0) {
        float a0 = 0.f, a1 = 0.f, a2 = 0.f, a3 = 0.f;
#pragma unroll
        for (int w = 0; w < 8; w++) { a0 += red[w][0]; a1 += red[w][1]; a2 += red[w][2]; a3 += red[w][3]; }
        const int bid = blockIdx.y * 16 + blockIdx.x;
        g_pp[bid * 4 + 0] = a0; g_pp[bid * 4 + 1] = a1;
        g_pp[bid * 4 + 2] = a2; g_pp[bid * 4 + 3] = a3;
    }
}

__global__ __launch_bounds__(256) void final_kernel(float* __restrict__ out)
{
    __shared__ float sL[256], sPs[256], sPc[256], sNs[256], sNc[256];
    const int t = threadIdx.x;
    sL[t]  = g_lossrow[t] + g_lossrow[t + 256] + g_lossrow[t + 512] + g_lossrow[t + 768];
    sPs[t] = g_pp[t * 4 + 0];
    sPc[t] = g_pp[t * 4 + 1];
    sNs[t] = g_pp[t * 4 + 2];
    sNc[t] = g_pp[t * 4 + 3];
    __syncthreads();
    for (int s = 128; s > 0; s >>= 1) {
        if (t < s) {
            sL[t] += sL[t + s]; sPs[t] += sPs[t + s]; sPc[t] += sPc[t + s];
            sNs[t] += sNs[t + s]; sNc[t] += sNc[t + s];
        }
        __syncthreads();
    }
    if (t == 0) {
        const float loss_cls = sL[0] / (float)B_;
        const float pos_l = sPs[0] / fmaxf(sPc[0], 1.f);
        const float neg_l = sNs[0] / fmaxf(sNc[0], 1.f);
        out[0] = loss_cls + pos_l + neg_l;
    }
}

// ------------------------- launch -------------------------
extern "C" void kernel_launch(void* const* d_in, const int* in_sizes, int n_in,
                              void* d_out, int out_size)
{
    const float* x    = (const float*)d_in[0];
    const int*   lb   = (const int*)  d_in[1];
    const float* mem  = (const float*)d_in[2];
    const float* fc_w = (const float*)d_in[3];
    const float* fc_b = (const float*)d_in[4];
    const float* p1_w = (const float*)d_in[5];
    const float* p1_b = (const float*)d_in[6];
    const float* p2_w = (const float*)d_in[7];
    const float* p2_b = (const float*)d_in[8];

    void *pxh = nullptr, *pmh = nullptr, *pup = nullptr;
    cudaGetSymbolAddress(&pxh, g_xh);
    cudaGetSymbolAddress(&pmh, g_mh);
    cudaGetSymbolAddress(&pup, g_u_part);

    // Order keeps ncu's capture slot on seen_kernel.
    gemm_xhmh<<<dim3(19, 12, 1), 256>>>(x, mem, fc_w, fc_b, (float*)pxh, (float*)pmh);
    gemm_u<<<dim3(16, 1, UZ), 256>>>((const float*)pxh, p2_w, (float*)pup);
    u_final_kernel<<<128, 256>>>(p2_b);                 // only needs gemm_u
    seen_kernel<<<dim3(16, SZ, 1), 256>>>(p1_w);        // profiled launch
    rowloss_kernel<<<128, 256>>>(lb, p1_b);
    pairs_kernel<<<dim3(16, 16, 1), 256>>>(lb);
    final_kernel<<<1, 256>>>((float*)d_out);
}

// round 14
// speedup vs baseline: 1.2665x; 1.2665x over previous
#include <cuda_runtime.h>
#include <math.h>

#define B_   1024
#define D_   768
#define E_   1536
#define C_   150
#define P_   64
#define CPAD 160
#define NC_  151
#define UZ   16          // split-K slices for u
#define SZ   16          // e-splits for seen

typedef unsigned long long ull;

// ------------------------- f32x2 packed-math helpers -------------------------
__device__ __forceinline__ ull pack2(float x, float y) {
    ull r; asm("mov.b64 %0, {%1,%2};" : "=l"(r) : "f"(x), "f"(y)); return r;
}
__device__ __forceinline__ void unpack2(ull v, float& x, float& y) {
    asm("mov.b64 {%0,%1}, %2;" : "=f"(x), "=f"(y) : "l"(v));
}
__device__ __forceinline__ ull ffma2(ull a, ull b, ull c) {
    ull d; asm("fma.rn.f32x2 %0, %1, %2, %3;" : "=l"(d) : "l"(a), "l"(b), "l"(c)); return d;
}
// relu(a + m) on both packed halves
__device__ __forceinline__ ull addrelu2(ull a, ull m) {
    ull r;
    asm("{\n\t"
        ".reg .b64 s;\n\t"
        ".reg .f32 lo, hi;\n\t"
        "add.rn.f32x2 s, %1, %2;\n\t"
        "mov.b64 {lo, hi}, s;\n\t"
        "max.f32 lo, lo, 0f00000000;\n\t"
        "max.f32 hi, hi, 0f00000000;\n\t"
        "mov.b64 %0, {lo, hi};\n\t"
        "}" : "=l"(r) : "l"(a), "l"(m));
    return r;
}

// ------------------------- static device scratch -------------------------
__device__ float g_xh[B_ * E_];                 // x @ Wx^T + fc_b
__device__ float g_mh[C_ * E_];                 // mem @ Wm^T
__device__ float g_seen_part[SZ * B_ * CPAD];   // e-split partials of logits
__device__ float g_u_part[UZ * B_ * P_];        // split-K partials of u
__device__ float g_un[B_ * P_];                 // normalized u
__device__ float g_sqn[B_];                     // ||un||^2 (post-normalize)
__device__ float g_lossrow[B_];
__device__ float g_pp[256 * 4];                 // per-block pair partials

// ------------------------- 256-thread f32x2 GEMM core (R11 version) -------------------------
// C[m0+i, n0+j] = sum_k A[m0+i, kbase+k] * W[n0+j, koff+kbase+k]  (+bias)
// BM=128, BN in {128, 64}; micro-tile 8 x (BN/16). A duplicated in smem
// (LDS.64 -> (a,a) operand); W pairs read as ulonglong2.
template <int BN, bool RELU_A>
__device__ __forceinline__ void gemm_core256(
    const float* __restrict__ A, int M, int m0, int lda,
    const float* __restrict__ W, int n0, int ldw, int koff,
    int kbase, int klen, const float* __restrict__ bias,
    float* __restrict__ out, int ldc)
{
    constexpr int MJ = BN / 16;          // cols per thread (8 or 4)
    constexpr int WL = BN / 64;          // W float4-loads per thread (2 or 1)
    __shared__ float As2[16][260];       // duplicated A: [k][2*row(+0/1)]
    __shared__ float Ws[16][BN + 4];

    const int t  = threadIdx.x;
    const int tx = t & 15;               // col group
    const int ty = t >> 4;               // row group (16 groups x 8 rows)

    ull acc[8][MJ / 2];
#pragma unroll
    for (int i = 0; i < 8; i++)
#pragma unroll
        for (int j = 0; j < MJ / 2; j++) acc[i][j] = 0ull;

    float4 pa[2], pw[WL];

    // prefetch first k-tile
    {
#pragma unroll
        for (int l = 0; l < 2; l++) {
            const int idx = t + 256 * l;
            const int row = idx >> 2, q = idx & 3;
            float4 v = make_float4(0.f, 0.f, 0.f, 0.f);
            const int am = m0 + row;
            if (am < M) v = *(const float4*)(A + (long long)am * lda + kbase + q * 4);
            if (RELU_A) {
                v.x = fmaxf(v.x, 0.f); v.y = fmaxf(v.y, 0.f);
                v.z = fmaxf(v.z, 0.f); v.w = fmaxf(v.w, 0.f);
            }
            pa[l] = v;
        }
#pragma unroll
        for (int l = 0; l < WL; l++) {
            const int idx = t + 256 * l;
            const int row = idx >> 2, q = idx & 3;
            pw[l] = *(const float4*)(W + (long long)(n0 + row) * ldw + koff + kbase + q * 4);
        }
    }

    const int nktiles = klen / 16;
    for (int kt = 0; kt < nktiles; kt++) {
        __syncthreads();
        // commit prefetched tile to smem
#pragma unroll
        for (int l = 0; l < 2; l++) {
            const int idx = t + 256 * l;
            const int row = idx >> 2, q = idx & 3;
            const float4 v = pa[l];
            *(ull*)&As2[q * 4 + 0][2 * row] = pack2(v.x, v.x);
            *(ull*)&As2[q * 4 + 1][2 * row] = pack2(v.y, v.y);
            *(ull*)&As2[q * 4 + 2][2 * row] = pack2(v.z, v.z);
            *(ull*)&As2[q * 4 + 3][2 * row] = pack2(v.w, v.w);
        }
#pragma unroll
        for (int l = 0; l < WL; l++) {
            const int idx = t + 256 * l;
            const int row = idx >> 2, q = idx & 3;
            const float4 v = pw[l];
            Ws[q * 4 + 0][row] = v.x; Ws[q * 4 + 1][row] = v.y;
            Ws[q * 4 + 2][row] = v.z; Ws[q * 4 + 3][row] = v.w;
        }
        __syncthreads();

        // prefetch next tile (kbase included in BOTH A and W paths)
        if (kt + 1 < nktiles) {
            const int kn = kbase + (kt + 1) * 16;
#pragma unroll
            for (int l = 0; l < 2; l++) {
                const int idx = t + 256 * l;
                const int row = idx >> 2, q = idx & 3;
                float4 v = make_float4(0.f, 0.f, 0.f, 0.f);
                const int am = m0 + row;
                if (am < M) v = *(const float4*)(A + (long long)am * lda + kn + q * 4);
                if (RELU_A) {
                    v.x = fmaxf(v.x, 0.f); v.y = fmaxf(v.y, 0.f);
                    v.z = fmaxf(v.z, 0.f); v.w = fmaxf(v.w, 0.f);
                }
                pa[l] = v;
            }
#pragma unroll
            for (int l = 0; l < WL; l++) {
                const int idx = t + 256 * l;
                const int row = idx >> 2, q = idx & 3;
                pw[l] = *(const float4*)(W + (long long)(n0 + row) * ldw + koff + kn + q * 4);
            }
        }

        // compute
#pragma unroll
        for (int kk = 0; kk < 16; kk++) {
            ull av[8];
#pragma unroll
            for (int i = 0; i < 8; i++)
                av[i] = *(const ull*)&As2[kk][2 * (ty * 8 + i)];
            ull bv[MJ / 2];
            if constexpr (MJ == 8) {
                const ulonglong2 w0 = *(const ulonglong2*)&Ws[kk][tx * 8];
                const ulonglong2 w1 = *(const ulonglong2*)&Ws[kk][tx * 8 + 4];
                bv[0] = w0.x; bv[1] = w0.y; bv[2] = w1.x; bv[3] = w1.y;
            } else {
                const ulonglong2 w0 = *(const ulonglong2*)&Ws[kk][tx * 4];
                bv[0] = w0.x; bv[1] = w0.y;
            }
#pragma unroll
            for (int i = 0; i < 8; i++)
#pragma unroll
                for (int j = 0; j < MJ / 2; j++)
                    acc[i][j] = ffma2(av[i], bv[j], acc[i][j]);
        }
    }

    const int nb = n0 + tx * MJ;
    float bvv[MJ];
#pragma unroll
    for (int q = 0; q < MJ; q++) bvv[q] = (bias != nullptr) ? bias[nb + q] : 0.f;
#pragma unroll
    for (int i = 0; i < 8; i++) {
        const int m = m0 + ty * 8 + i;
        if (m >= M) continue;
        float o[MJ];
#pragma unroll
        for (int jp = 0; jp < MJ / 2; jp++) unpack2(acc[i][jp], o[2 * jp], o[2 * jp + 1]);
#pragma unroll
        for (int q = 0; q < MJ; q++) o[q] += bvv[q];
#pragma unroll
        for (int q = 0; q < MJ / 4; q++)
            *(float4*)(out + (long long)m * ldc + nb + 4 * q) =
                make_float4(o[4 * q], o[4 * q + 1], o[4 * q + 2], o[4 * q + 3]);
    }
}

// combined xh (bx<8) and mh (bx>=8) launch; 2 CTAs/SM for latency hiding
__global__ __launch_bounds__(256, 2) void gemm_xhmh(
    const float* __restrict__ x, const float* __restrict__ mem,
    const float* __restrict__ fc_w, const float* __restrict__ fc_b,
    float* __restrict__ xh, float* __restrict__ mh)
{
    const int bx = blockIdx.x;
    const int n0 = blockIdx.y * 128;
    const float* A; int M, m0, koff; const float* bias; float* out;
    if (bx < 8) { A = x;   M = B_; m0 = bx * 128;       koff = 0;  bias = fc_b;   out = xh; }
    else        { A = mem; M = C_; m0 = (bx - 8) * 128; koff = D_; bias = nullptr; out = mh; }
    gemm_core256<128, false>(A, M, m0, D_, fc_w, n0, E_, koff, 0, D_, bias, out, E_);
}

// u partials: relu(xh) @ p2_w^T, split-K = UZ chunks of E_/UZ
__global__ __launch_bounds__(256, 2) void gemm_u(
    const float* __restrict__ xh, const float* __restrict__ p2w,
    float* __restrict__ outbase)
{
    const int z = blockIdx.z;
    constexpr int CHUNK = E_ / UZ;   // 96
    gemm_core256<64, true>(xh, B_, blockIdx.x * 128, E_, p2w, 0, E_, 0,
                           z * CHUNK, CHUNK, nullptr,
                           outbase + (long long)z * (B_ * P_), P_);
}

// ------------------------- seen/unseen fused (R12 version, measured 36.7us) ----
// part[z][b][c] = sum_{e in z-chunk(96)} relu(xh[b,e] + mh_ext[c,e]) * p1w[e]
// class 150 == "unseen" (mh row = 0). Block: 64 b x 160 c; grid (16, SZ) = 256.
__global__ __launch_bounds__(256) void seen_kernel(const float* __restrict__ p1w)
{
    __shared__ float As[16][68];     // [e][b]
    __shared__ float Ms2[16][324];   // [e][2c / 2c+1] duplicated
    __shared__ float Wsh[16];

    const int t  = threadIdx.x;
    const int tx = t & 31;           // c lane
    const int ty = t >> 5;           // b group (0..7)
    const int b0 = blockIdx.x * 64;
    const int e0 = blockIdx.y * 96;  // SZ splits of 96

    ull acc[4][5];
#pragma unroll
    for (int p = 0; p < 4; p++)
#pragma unroll
        for (int j = 0; j < 5; j++) acc[p][j] = 0ull;

    for (int ch = 0; ch < 6; ch++) {
        const int ec = e0 + ch * 16;
        __syncthreads();
        // xh tile 64 x 16 : 256 float4, 1/thread
        {
            const int row = t >> 2, c4 = t & 3;
            const float4 v = *(const float4*)(g_xh + (long long)(b0 + row) * E_ + ec + c4 * 4);
            As[c4 * 4 + 0][row] = v.x; As[c4 * 4 + 1][row] = v.y;
            As[c4 * 4 + 2][row] = v.z; As[c4 * 4 + 3][row] = v.w;
        }
        // mh tile 160 x 16 duplicated : 640 float4
        for (int idx = t; idx < 640; idx += 256) {
            const int c = idx >> 2, c4 = idx & 3;
            float4 v = make_float4(0.f, 0.f, 0.f, 0.f);
            if (c < C_) v = *(const float4*)(g_mh + (long long)c * E_ + ec + c4 * 4);
            *(ull*)&Ms2[c4 * 4 + 0][2 * c] = pack2(v.x, v.x);
            *(ull*)&Ms2[c4 * 4 + 1][2 * c] = pack2(v.y, v.y);
            *(ull*)&Ms2[c4 * 4 + 2][2 * c] = pack2(v.z, v.z);
            *(ull*)&Ms2[c4 * 4 + 3][2 * c] = pack2(v.w, v.w);
        }
        if (t < 16) Wsh[t] = p1w[ec + t];
        __syncthreads();

#pragma unroll 4
        for (int e = 0; e < 16; e++) {
            const float w = Wsh[e];
            const ull w2 = pack2(w, w);
            ull av[4];
#pragma unroll
            for (int p = 0; p < 4; p++)
                av[p] = *(const ull*)&As[e][ty * 8 + 2 * p];
            ull m2[5];
#pragma unroll
            for (int j = 0; j < 5; j++)
                m2[j] = *(const ull*)&Ms2[e][2 * (tx + 32 * j)];
#pragma unroll
            for (int j = 0; j < 5; j++)
#pragma unroll
                for (int p = 0; p < 4; p++)
                    acc[p][j] = ffma2(addrelu2(av[p], m2[j]), w2, acc[p][j]);
        }
    }

    float* outp = g_seen_part + (long long)blockIdx.y * (B_ * CPAD);
#pragma unroll
    for (int p = 0; p < 4; p++) {
        float f0, f1;
#pragma unroll
        for (int j = 0; j < 5; j++) {
            unpack2(acc[p][j], f0, f1);
            const int c = tx + 32 * j;
            outp[(long long)(b0 + ty * 8 + 2 * p)     * CPAD + c] = f0;
            outp[(long long)(b0 + ty * 8 + 2 * p + 1) * CPAD + c] = f1;
        }
    }
}

// ------------------------- warp reduce helpers -------------------------
__device__ __forceinline__ float warp_max(float v) {
#pragma unroll
    for (int o = 16; o > 0; o >>= 1) v = fmaxf(v, __shfl_xor_sync(0xffffffffu, v, o));
    return v;
}
__device__ __forceinline__ float warp_sum(float v) {
#pragma unroll
    for (int o = 16; o > 0; o >>= 1) v += __shfl_xor_sync(0xffffffffu, v, o);
    return v;
}

// per-row: sum e-split partials -> logits, then masked-softmax losses
__global__ __launch_bounds__(256) void rowloss_kernel(const int* __restrict__ lb,
                                                      const float* __restrict__ p1b)
{
    const int warp = threadIdx.x >> 5;
    const int lane = threadIdx.x & 31;
    const int b = blockIdx.x * 8 + warp;
    if (b >= B_) return;
    const int label = lb[b];
    const float bias0 = p1b[0];

    float raw[5];
#pragma unroll
    for (int it = 0; it < 5; it++) {
        const int c = lane + 32 * it;
        float s = bias0;
        if (c < NC_) {
#pragma unroll
            for (int zz = 0; zz < SZ; zz++)
                s += g_seen_part[(long long)zz * (B_ * CPAD) + (long long)b * CPAD + c];
            raw[it] = s;
        } else raw[it] = -3.0e38f;
    }

    const float l150 = __shfl_sync(0xffffffffu, raw[4], NC_ - 1 - 128);
    float lv = -3.0e38f;
#pragma unroll
    for (int it = 0; it < 5; it++)
        if (lane + 32 * it == label) lv = raw[it];
    lv = warp_max(lv);

    float vmax = -3.0e38f;
    float ex[5];
#pragma unroll
    for (int it = 0; it < 5; it++) {
        float v = raw[it];
        if (label < C_ && (lane + 32 * it) == label) v = -3.0e38f;
        ex[it] = v;
        vmax = fmaxf(vmax, v);
    }
    const float m2 = warp_max(vmax);
    float s = 0.f;
#pragma unroll
    for (int it = 0; it < 5; it++)
        if (ex[it] > -1.0e38f) s += expf(ex[it] - m2);
    const float s2 = warp_sum(s);

    if (lane == 0) {
        const float loss2 = -(l150 - (m2 + logf(s2)));
        float loss1 = 0.f;
        if (label < C_) {
            const float mm = fmaxf(lv, l150);
            const float ss = expf(lv - mm) + expf(l150 - mm);
            loss1 = -(lv - (mm + logf(ss)));
        }
        g_lossrow[b] = loss1 + loss2;
    }
}

// finalize u: sum split-K partials + bias, L2-normalize, store ||un||^2
__global__ __launch_bounds__(256) void u_final_kernel(const float* __restrict__ p2b)
{
    const int warp = threadIdx.x >> 5;
    const int lane = threadIdx.x & 31;
    const int b = blockIdx.x * 8 + warp;
    if (b >= B_) return;

    float v0 = p2b[lane], v1 = p2b[lane + 32];
#pragma unroll
    for (int z = 0; z < UZ; z++) {
        const float* p = g_u_part + (long long)z * (B_ * P_) + (long long)b * P_;
        v0 += p[lane];
        v1 += p[lane + 32];
    }
    const float n2 = warp_sum(v0 * v0 + v1 * v1);
    const float n = fmaxf(sqrtf(n2), 1e-12f);
    const float u0 = v0 / n, u1 = v1 / n;
    g_un[(long long)b * P_ + lane]      = u0;
    g_un[(long long)b * P_ + lane + 32] = u1;
    const float sq = warp_sum(u0 * u0 + u1 * u1);
    if (lane == 0) g_sqn[b] = sq;
}

// pairwise contrastive terms: 64x64 pair tile / block, K=64 dots via FFMA2
__global__ __launch_bounds__(256) void pairs_kernel(const int* __restrict__ lb)
{
    __shared__ float Ui[64][68];
    __shared__ float Uj[64][68];
    __shared__ int   lbi[64], lbj[64];
    __shared__ float sqi[64], sqj[64];
    __shared__ float red[8][4];

    const int t  = threadIdx.x;
    const int tx = t & 15, ty = t >> 4;
    const int i0 = blockIdx.x * 64, j0 = blockIdx.y * 64;

    for (int idx = t; idx < 1024; idx += 256) {
        const int row = idx >> 4, c4 = idx & 15;
        float4 v = *(const float4*)(g_un + (long long)(i0 + row) * P_ + c4 * 4);
        Ui[c4 * 4 + 0][row] = v.x; Ui[c4 * 4 + 1][row] = v.y;
        Ui[c4 * 4 + 2][row] = v.z; Ui[c4 * 4 + 3][row] = v.w;
        v = *(const float4*)(g_un + (long long)(j0 + row) * P_ + c4 * 4);
        Uj[c4 * 4 + 0][row] = v.x; Uj[c4 * 4 + 1][row] = v.y;
        Uj[c4 * 4 + 2][row] = v.z; Uj[c4 * 4 + 3][row] = v.w;
    }
    if (t < 64)       { lbi[t] = lb[i0 + t];           sqi[t] = g_sqn[i0 + t]; }
    else if (t < 128) { lbj[t - 64] = lb[j0 + t - 64]; sqj[t - 64] = g_sqn[j0 + t - 64]; }
    __syncthreads();

    ull dot2[4][2];
#pragma unroll
    for (int i = 0; i < 4; i++) { dot2[i][0] = 0ull; dot2[i][1] = 0ull; }

#pragma unroll 8
    for (int kk = 0; kk < 64; kk++) {
        const float4 a = *(const float4*)&Ui[kk][ty * 4];
        const float4 b = *(const float4*)&Uj[kk][tx * 4];
        const ull b01 = pack2(b.x, b.y);
        const ull b23 = pack2(b.z, b.w);
        const float aa[4] = {a.x, a.y, a.z, a.w};
#pragma unroll
        for (int i = 0; i < 4; i++) {
            const ull ai = pack2(aa[i], aa[i]);
            dot2[i][0] = ffma2(ai, b01, dot2[i][0]);
            dot2[i][1] = ffma2(ai, b23, dot2[i][1]);
        }
    }

    float ps = 0.f, pc = 0.f, ns = 0.f, nc = 0.f;
#pragma unroll
    for (int i = 0; i < 4; i++) {
        const int li = ty * 4 + i;
        float dd[4];
        unpack2(dot2[i][0], dd[0], dd[1]);
        unpack2(dot2[i][1], dd[2], dd[3]);
#pragma unroll
        for (int j = 0; j < 4; j++) {
            const int ljj = tx * 4 + j;
            const float sq = sqi[li] + sqj[ljj] - 2.f * dd[j];
            const float d = (sq > 0.f) ? sqrtf(fmaxf(sq, 1e-16f)) : 0.f;
            if (lbi[li] == lbj[ljj]) {
                if ((i0 + li) != (j0 + ljj)) { ps += fmaxf(d - 0.7f, 0.f); pc += 1.f; }
            } else {
                ns += fmaxf(1.4f - d, 0.f); nc += 1.f;
            }
        }
    }
    ps = warp_sum(ps); pc = warp_sum(pc); ns = warp_sum(ns); nc = warp_sum(nc);
    const int warp = t >> 5, lane = t & 31;
    if (lane == 0) { red[warp][0] = ps; red[warp][1] = pc; red[warp][2] = ns; red[warp][3] = nc; }
    __syncthreads();
    if (t == 0) {
        float a0 = 0.f, a1 = 0.f, a2 = 0.f, a3 = 0.f;
#pragma unroll
        for (int w = 0; w < 8; w++) { a0 += red[w][0]; a1 += red[w][1]; a2 += red[w][2]; a3 += red[w][3]; }
        const int bid = blockIdx.y * 16 + blockIdx.x;
        g_pp[bid * 4 + 0] = a0; g_pp[bid * 4 + 1] = a1;
        g_pp[bid * 4 + 2] = a2; g_pp[bid * 4 + 3] = a3;
    }
}

__global__ __launch_bounds__(256) void final_kernel(float* __restrict__ out)
{
    __shared__ float sL[256], sPs[256], sPc[256], sNs[256], sNc[256];
    const int t = threadIdx.x;
    sL[t]  = g_lossrow[t] + g_lossrow[t + 256] + g_lossrow[t + 512] + g_lossrow[t + 768];
    sPs[t] = g_pp[t * 4 + 0];
    sPc[t] = g_pp[t * 4 + 1];
    sNs[t] = g_pp[t * 4 + 2];
    sNc[t] = g_pp[t * 4 + 3];
    __syncthreads();
    for (int s = 128; s > 0; s >>= 1) {
        if (t < s) {
            sL[t] += sL[t + s]; sPs[t] += sPs[t + s]; sPc[t] += sPc[t + s];
            sNs[t] += sNs[t + s]; sNc[t] += sNc[t + s];
        }
        __syncthreads();
    }
    if (t == 0) {
        const float loss_cls = sL[0] / (float)B_;
        const float pos_l = sPs[0] / fmaxf(sPc[0], 1.f);
        const float neg_l = sNs[0] / fmaxf(sNc[0], 1.f);
        out[0] = loss_cls + pos_l + neg_l;
    }
}

// ------------------------- launch -------------------------
extern "C" void kernel_launch(void* const* d_in, const int* in_sizes, int n_in,
                              void* d_out, int out_size)
{
    const float* x    = (const float*)d_in[0];
    const int*   lb   = (const int*)  d_in[1];
    const float* mem  = (const float*)d_in[2];
    const float* fc_w = (const float*)d_in[3];
    const float* fc_b = (const float*)d_in[4];
    const float* p1_w = (const float*)d_in[5];
    const float* p1_b = (const float*)d_in[6];
    const float* p2_w = (const float*)d_in[7];
    const float* p2_b = (const float*)d_in[8];

    void *pxh = nullptr, *pmh = nullptr, *pup = nullptr;
    cudaGetSymbolAddress(&pxh, g_xh);
    cudaGetSymbolAddress(&pmh, g_mh);
    cudaGetSymbolAddress(&pup, g_u_part);

    // Order keeps ncu's capture slot on seen_kernel.
    gemm_xhmh<<<dim3(10, 12, 1), 256>>>(x, mem, fc_w, fc_b, (float*)pxh, (float*)pmh);
    gemm_u<<<dim3(8, 1, UZ), 256>>>((const float*)pxh, p2_w, (float*)pup);
    u_final_kernel<<<128, 256>>>(p2_b);                 // only needs gemm_u
    seen_kernel<<<dim3(16, SZ, 1), 256>>>(p1_w);        // profiled launch
    rowloss_kernel<<<128, 256>>>(lb, p1_b);
    pairs_kernel<<<dim3(16, 16, 1), 256>>>(lb);
    final_kernel<<<1, 256>>>((float*)d_out);
}